// round 11
// baseline (speedup 1.0000x reference)
#include <cuda_runtime.h>
#include <stdint.h>

// Fixed problem shapes
#define NB 32
#define NS 32
#define NW 30
#define NE 300
#define NEV 75                   // float4 per embedding row (300 floats)
#define NSENT (NB * NS)          // 1024
#define EMB_ELEMS (NSENT * NW * NE)          // 9,216,000
#define OFF_SHARE  EMB_ELEMS
#define OFF_MASK   (2 * EMB_ELEMS)           // 18,432,000
#define OFF_WMASK  (OFF_MASK + NSENT * NW)
#define OFF_SMASK  (OFF_WMASK + NSENT * NW)

#define SENT_VEC  (NW * NEV)     // 2250 float4 per sentence
#define BLOCK     512
#define NITER     5              // 4 full + 1 tail (202 lanes)

__global__ __launch_bounds__(BLOCK, 4) void embed_fused_kernel(
    const int* __restrict__ input_var,        // [1024*30] int32 tokens
    const float* __restrict__ W_emb,          // [50000*300]
    float* __restrict__ out)
{
    const int sent = blockIdx.x;        // 0..1023
    const int tid  = threadIdx.x;

    __shared__ int s_tok[NW];
    __shared__ unsigned s_kmask;        // bit w set => token w kept (before first zero)

    // Warp 0: load tokens + compute all masks with one ballot
    if (tid < 32) {
        const int t = (tid < NW) ? input_var[sent * NW + tid] : 1;
        if (tid < NW) s_tok[tid] = t;
        const unsigned nz = __ballot_sync(0xFFFFFFFFu, t != 0);
        const unsigned firstzero = ~nz;                 // lowest set bit = first zero
        const unsigned keepmask  = (firstzero - 1u) & ~firstzero & 0x3FFFFFFFu;
        if (tid == 0) s_kmask = keepmask;
        if (tid < NW) {
            out[OFF_MASK  + sent * NW + tid] = (keepmask >> tid & 1u) ? 1.0f : 0.0f;
            out[OFF_WMASK + sent * NW + tid] = (t != 0) ? 1.0f : 0.0f;
        }
        if (tid == 0) {
            out[OFF_SMASK + sent] = ((nz & 0x3FFFFFFFu) != 0u) ? 1.0f : 0.0f;
        }
    }
    __syncthreads();

    const unsigned kmask = s_kmask;
    const float4* __restrict__ emb4 = (const float4*)W_emb;
    float4* __restrict__ out_e = (float4*)out + (size_t)sent * SENT_VEC;
    float4* __restrict__ out_s = (float4*)(out + OFF_SHARE) + (size_t)sent * SENT_VEC;

    // Phase 1: batched gathers. i=0..3 provably in-bounds (tid+1536 <= 2047 < 2250)
    // -> 4 unconditional LDG.128 front-batched; only the tail is predicated.
    float4 vals[NITER];
    #pragma unroll
    for (int i = 0; i < 4; i++) {
        const int v = tid + i * BLOCK;
        const int w = v / NEV;
        const int j = v - w * NEV;
        vals[i] = __ldg(&emb4[(size_t)s_tok[w] * NEV + j]);
    }
    const int v4 = tid + 4 * BLOCK;
    if (v4 < SENT_VEC) {
        const int w = v4 / NEV;
        const int j = v4 - w * NEV;
        vals[4] = __ldg(&emb4[(size_t)s_tok[w] * NEV + j]);
    }

    // Phase 2: streaming stores; rare truncated token -> row 0 (predicated reload)
    #pragma unroll
    for (int i = 0; i < NITER; i++) {
        const int v = tid + i * BLOCK;
        if (i < 4 || v < SENT_VEC) {
            const int w = v / NEV;
            const int j = v - w * NEV;
            __stcs(&out_e[v], vals[i]);
            float4 x = vals[i];
            if (!(kmask >> w & 1u)) x = __ldg(&emb4[j]);   // row 0
            __stcs(&out_s[v], x);
        }
    }
}

extern "C" void kernel_launch(void* const* d_in, const int* in_sizes, int n_in,
                              void* d_out, int out_size) {
    const int*   input_var = (const int*)d_in[0];
    const float* W_emb     = (const float*)d_in[1];
    float*       out       = (float*)d_out;

    embed_fused_kernel<<<NSENT, BLOCK>>>(input_var, W_emb, out);
}

// round 12
// speedup vs baseline: 1.0132x; 1.0132x over previous
#include <cuda_runtime.h>
#include <stdint.h>

// Fixed problem shapes
#define NB 32
#define NS 32
#define NW 30
#define NE 300
#define NEV 75                   // float4 per embedding row (300 floats)
#define NSENT (NB * NS)          // 1024
#define EMB_ELEMS (NSENT * NW * NE)          // 9,216,000
#define OFF_SHARE  EMB_ELEMS
#define OFF_MASK   (2 * EMB_ELEMS)           // 18,432,000
#define OFF_WMASK  (OFF_MASK + NSENT * NW)
#define OFF_SMASK  (OFF_WMASK + NSENT * NW)

#define SENT_VEC  (NW * NEV)     // 2250 float4 per sentence
#define BLOCK     512
#define GRID      512            // single wave: 512 <= 148*4 CTA slots
#define NITER     5              // 4 full + 1 tail (202 lanes)

__global__ __launch_bounds__(BLOCK, 4) void embed_fused_kernel(
    const int* __restrict__ input_var,        // [1024*30] int32 tokens
    const float* __restrict__ W_emb,          // [50000*300]
    float* __restrict__ out)
{
    const int tid = threadIdx.x;
    const float4* __restrict__ emb4 = (const float4*)W_emb;

    __shared__ int s_tok[NW];
    __shared__ unsigned s_kmask;

    #pragma unroll
    for (int pass = 0; pass < 2; pass++) {
        const int sent = blockIdx.x + pass * GRID;   // 0..511, then 512..1023

        if (pass) __syncthreads();   // protect s_tok/s_kmask reuse across passes

        // Warp 0: load tokens + all masks via one ballot
        if (tid < 32) {
            const int t = (tid < NW) ? input_var[sent * NW + tid] : 1;
            if (tid < NW) s_tok[tid] = t;
            const unsigned nz = __ballot_sync(0xFFFFFFFFu, t != 0);
            const unsigned firstzero = ~nz;             // lowest set bit = first zero
            const unsigned keepmask  = (firstzero - 1u) & ~firstzero & 0x3FFFFFFFu;
            if (tid == 0) s_kmask = keepmask;
            if (tid < NW) {
                out[OFF_MASK  + sent * NW + tid] = (keepmask >> tid & 1u) ? 1.0f : 0.0f;
                out[OFF_WMASK + sent * NW + tid] = (t != 0) ? 1.0f : 0.0f;
            }
            if (tid == 0) {
                out[OFF_SMASK + sent] = ((nz & 0x3FFFFFFFu) != 0u) ? 1.0f : 0.0f;
            }
        }
        __syncthreads();

        const unsigned kmask = s_kmask;
        float4* __restrict__ out_e = (float4*)out + (size_t)sent * SENT_VEC;
        float4* __restrict__ out_s = (float4*)(out + OFF_SHARE) + (size_t)sent * SENT_VEC;

        // Phase 1: batched gathers. i=0..3 provably in-bounds (tid+1536 < 2250)
        float4 vals[NITER];
        #pragma unroll
        for (int i = 0; i < 4; i++) {
            const int v = tid + i * BLOCK;
            const int w = v / NEV;
            const int j = v - w * NEV;
            vals[i] = __ldg(&emb4[(size_t)s_tok[w] * NEV + j]);
        }
        const int v4 = tid + 4 * BLOCK;
        if (v4 < SENT_VEC) {
            const int w = v4 / NEV;
            const int j = v4 - w * NEV;
            vals[4] = __ldg(&emb4[(size_t)s_tok[w] * NEV + j]);
        }

        // Phase 2: streaming stores; rare truncated token -> row 0
        #pragma unroll
        for (int i = 0; i < NITER; i++) {
            const int v = tid + i * BLOCK;
            if (i < 4 || v < SENT_VEC) {
                const int w = v / NEV;
                const int j = v - w * NEV;
                __stcs(&out_e[v], vals[i]);
                float4 x = vals[i];
                if (!(kmask >> w & 1u)) x = __ldg(&emb4[j]);   // row 0
                __stcs(&out_s[v], x);
            }
        }
    }
}

extern "C" void kernel_launch(void* const* d_in, const int* in_sizes, int n_in,
                              void* d_out, int out_size) {
    const int*   input_var = (const int*)d_in[0];
    const float* W_emb     = (const float*)d_in[1];
    float*       out       = (float*)d_out;

    embed_fused_kernel<<<GRID, BLOCK>>>(input_var, W_emb, out);
}